// round 1
// baseline (speedup 1.0000x reference)
#include <cuda_runtime.h>
#include <cuda_bf16.h>

// Problem shape (fixed per reference setup_inputs)
#define BH   16          // B*H = 4*4
#define NSEQ 4096
#define DIM  64
#define ROWS (BH * NSEQ)             // 65536
#define ELEMS (ROWS * DIM)           // 4,194,304 floats

// Scratch (allocation-free rule: __device__ globals)
__device__ float g_xn[ELEMS];    // normalized x for current block
__device__ float g_tmp[ELEMS];   // output of block 1 / input of block 2

// ---------------------------------------------------------------------------
// L2-normalize each length-64 row: one warp per row.
// ---------------------------------------------------------------------------
__global__ void norm_kernel(const float* __restrict__ x, float* __restrict__ xn) {
    int gtid = blockIdx.x * blockDim.x + threadIdx.x;
    int row  = gtid >> 5;
    int lane = gtid & 31;
    if (row >= ROWS) return;
    const float* xr = x + (size_t)row * DIM;
    float a = xr[lane];
    float b = xr[lane + 32];
    float ss = a * a + b * b;
    #pragma unroll
    for (int off = 16; off > 0; off >>= 1)
        ss += __shfl_xor_sync(0xFFFFFFFFu, ss, off);
    float nrm = sqrtf(ss);
    float inv = 1.0f / fmaxf(nrm, 1e-12f);
    float* o = xn + (size_t)row * DIM;
    o[lane]      = a * inv;
    o[lane + 32] = b * inv;
}

// ---------------------------------------------------------------------------
// One attention block:
//   out[n,:] = relu( (softmax_row(xn·xn^T * scale) @ x) @ W^T + x[n,:] )
// Key fact: rows of xn are unit vectors -> row max of logits is exactly
// scale (the diagonal), so no online max tracking is needed:
//   p_j = exp(scale*(s_j - 1)) in (0, 1].
// Grid: (NSEQ/128, BH), 128 threads, 1 query row per thread.
// ---------------------------------------------------------------------------
__global__ void __launch_bounds__(128)
attn_kernel(const float* __restrict__ x,      // raw block input (V + residual)
            const float* __restrict__ xn,     // normalized input (Q, K)
            const float* __restrict__ W,      // [64,64] row-major, applied as @ W^T
            const float* __restrict__ alpha_p,
            float* __restrict__ out) {
    __shared__ float4 ksm[64 * 16];
    __shared__ float4 vsm[64 * 16];
    __shared__ float4 wsm[64 * 16];

    const int tid = threadIdx.x;
    const int bh  = blockIdx.y;
    const size_t base = (size_t)bh * NSEQ * DIM;
    const int row = blockIdx.x * 128 + tid;

    // Stage W once (16 KB)
    const float4* W4 = (const float4*)W;
    #pragma unroll
    for (int i = 0; i < 8; i++)
        wsm[tid + i * 128] = W4[tid + i * 128];

    const float alpha = alpha_p[0];
    const float scale = 1.0f / fmaxf(alpha, 0.01f);

    // Query row (normalized) in registers
    const float4* q4 = (const float4*)(xn + base + (size_t)row * DIM);
    float4 q[16];
    #pragma unroll
    for (int i = 0; i < 16; i++) q[i] = q4[i];

    float4 O[16];
    #pragma unroll
    for (int i = 0; i < 16; i++) O[i] = make_float4(0.f, 0.f, 0.f, 0.f);
    float l = 0.0f;

    const float4* K4 = (const float4*)(xn + base);
    const float4* V4 = (const float4*)(x  + base);

    for (int kt = 0; kt < NSEQ; kt += 64) {
        __syncthreads();   // previous tile fully consumed (also orders W stage)
        const float4* ks = K4 + (size_t)kt * 16;
        const float4* vs = V4 + (size_t)kt * 16;
        #pragma unroll
        for (int i = 0; i < 8; i++) {
            ksm[tid + i * 128] = ks[tid + i * 128];
            vsm[tid + i * 128] = vs[tid + i * 128];
        }
        __syncthreads();

        #pragma unroll 1
        for (int j = 0; j < 64; j++) {
            // dot(q, k_j): 4 independent accumulator chains
            const float4* kr = &ksm[j * 16];
            float4 acc = make_float4(0.f, 0.f, 0.f, 0.f);
            #pragma unroll
            for (int i = 0; i < 16; i++) {
                float4 kv = kr[i];
                acc.x = fmaf(q[i].x, kv.x, acc.x);
                acc.y = fmaf(q[i].y, kv.y, acc.y);
                acc.z = fmaf(q[i].z, kv.z, acc.z);
                acc.w = fmaf(q[i].w, kv.w, acc.w);
            }
            float s = (acc.x + acc.y) + (acc.z + acc.w);
            // p = exp(scale*(s - 1)); row max is the diagonal (s==1)
            float p = __expf(fmaf(s, scale, -scale));
            l += p;
            const float4* vr = &vsm[j * 16];
            #pragma unroll
            for (int i = 0; i < 16; i++) {
                float4 vv = vr[i];
                O[i].x = fmaf(p, vv.x, O[i].x);
                O[i].y = fmaf(p, vv.y, O[i].y);
                O[i].z = fmaf(p, vv.z, O[i].z);
                O[i].w = fmaf(p, vv.w, O[i].w);
            }
        }
    }

    // av = O / l
    const float invl = 1.0f / l;
    #pragma unroll
    for (int i = 0; i < 16; i++) {
        O[i].x *= invl; O[i].y *= invl; O[i].z *= invl; O[i].w *= invl;
    }

    // Epilogue: y[e] = relu( sum_d av[d]*W[e][d] + x[row][e] )
    const float4* xr4  = (const float4*)(x + base + (size_t)row * DIM);
    float4*       out4 = (float4*)(out + base + (size_t)row * DIM);
    #pragma unroll 1
    for (int e0 = 0; e0 < 64; e0 += 4) {
        float r[4];
        #pragma unroll
        for (int k = 0; k < 4; k++) {
            const float4* wr = &wsm[(e0 + k) * 16];
            float4 acc = make_float4(0.f, 0.f, 0.f, 0.f);
            #pragma unroll
            for (int i = 0; i < 16; i++) {
                float4 wv = wr[i];
                acc.x = fmaf(O[i].x, wv.x, acc.x);
                acc.y = fmaf(O[i].y, wv.y, acc.y);
                acc.z = fmaf(O[i].z, wv.z, acc.z);
                acc.w = fmaf(O[i].w, wv.w, acc.w);
            }
            r[k] = (acc.x + acc.y) + (acc.z + acc.w);
        }
        float4 xr = xr4[e0 >> 2];
        float4 res;
        res.x = fmaxf(r[0] + xr.x, 0.0f);
        res.y = fmaxf(r[1] + xr.y, 0.0f);
        res.z = fmaxf(r[2] + xr.z, 0.0f);
        res.w = fmaxf(r[3] + xr.w, 0.0f);
        out4[e0 >> 2] = res;
    }
}

// ---------------------------------------------------------------------------
// Driver: two blocks. Graph-capturable: kernel launches only.
// ---------------------------------------------------------------------------
extern "C" void kernel_launch(void* const* d_in, const int* in_sizes, int n_in,
                              void* d_out, int out_size) {
    const float* x      = (const float*)d_in[0];
    const float* W1     = (const float*)d_in[1];
    const float* W2     = (const float*)d_in[2];
    const float* alpha1 = (const float*)d_in[3];
    const float* alpha2 = (const float*)d_in[4];
    float* out = (float*)d_out;

    float* xn;  cudaGetSymbolAddress((void**)&xn,  g_xn);
    float* tmp; cudaGetSymbolAddress((void**)&tmp, g_tmp);

    dim3 ngrid((ROWS * 32 + 127) / 128);
    dim3 agrid(NSEQ / 128, BH);

    // Block 1: x -> tmp
    norm_kernel<<<ngrid, 128>>>(x, xn);
    attn_kernel<<<agrid, 128>>>(x, xn, W1, alpha1, tmp);
    // Block 2: tmp -> out
    norm_kernel<<<ngrid, 128>>>(tmp, xn);
    attn_kernel<<<agrid, 128>>>(tmp, xn, W2, alpha2, out);
}

// round 3
// speedup vs baseline: 8.7523x; 8.7523x over previous
#include <cuda_runtime.h>
#include <cuda_bf16.h>
#include <cstdint>

#define BH   16
#define NSEQ 4096
#define DIM  64
#define ROWS (BH * NSEQ)
#define ELEMS (ROWS * DIM)

// Scratch (__device__ globals per allocation-free rule)
__device__ __nv_bfloat16 g_qk[ELEMS];   // normalized x, bf16, [bh][n][d]
__device__ __nv_bfloat16 g_vt[ELEMS];   // x transposed,  bf16, [bh][d][n]
__device__ float         g_tmp[ELEMS];  // block-1 output

// ---------------------------------------------------------------------------
// helpers
// ---------------------------------------------------------------------------
__device__ __forceinline__ uint32_t smem_u32(const void* p) {
    uint32_t a;
    asm("{ .reg .u64 t; cvta.to.shared.u64 t, %1; cvt.u32.u64 %0, t; }" : "=r"(a) : "l"(p));
    return a;
}
__device__ __forceinline__ uint32_t lds32(uint32_t a) {
    uint32_t v;
    asm volatile("ld.shared.b32 %0, [%1];" : "=r"(v) : "r"(a));
    return v;
}
__device__ __forceinline__ void sts32(uint32_t a, uint32_t v) {
    asm volatile("st.shared.b32 [%0], %1;" :: "r"(a), "r"(v));
}
__device__ __forceinline__ float4 lds128(uint32_t a) {
    float4 v;
    asm volatile("ld.shared.v4.f32 {%0,%1,%2,%3}, [%4];"
                 : "=f"(v.x), "=f"(v.y), "=f"(v.z), "=f"(v.w) : "r"(a));
    return v;
}
__device__ __forceinline__ uint32_t packbf(float lo, float hi) {
    uint32_t r;
    asm("cvt.rn.satfinite.bf16x2.f32 %0, %1, %2;" : "=r"(r) : "f"(hi), "f"(lo));
    return r;
}
__device__ __forceinline__ void mma_bf16(float c[4], const uint32_t a[4],
                                         uint32_t b0, uint32_t b1) {
    asm volatile(
        "mma.sync.aligned.m16n8k16.row.col.f32.bf16.bf16.f32 "
        "{%0,%1,%2,%3},{%4,%5,%6,%7},{%8,%9},{%0,%1,%2,%3};"
        : "+f"(c[0]), "+f"(c[1]), "+f"(c[2]), "+f"(c[3])
        : "r"(a[0]), "r"(a[1]), "r"(a[2]), "r"(a[3]), "r"(b0), "r"(b1));
}
#define CP_ASYNC16(dst, src) \
    asm volatile("cp.async.cg.shared.global [%0], [%1], 16;" :: "r"(dst), "l"(src))
#define CP_COMMIT() asm volatile("cp.async.commit_group;" ::: "memory")
#define CP_WAIT0()  asm volatile("cp.async.wait_group 0;" ::: "memory")

// ---------------------------------------------------------------------------
// Prep 1: L2-normalize rows, convert to bf16 (one warp per row)
// ---------------------------------------------------------------------------
__global__ void norm_bf16_kernel(const float* __restrict__ x, __nv_bfloat16* __restrict__ qn) {
    int gtid = blockIdx.x * blockDim.x + threadIdx.x;
    int row = gtid >> 5, lane = gtid & 31;
    if (row >= ROWS) return;
    const float* xr = x + (size_t)row * DIM;
    float a = xr[lane], b = xr[lane + 32];
    float ss = a * a + b * b;
    #pragma unroll
    for (int off = 16; off > 0; off >>= 1) ss += __shfl_xor_sync(0xFFFFFFFFu, ss, off);
    float inv = 1.0f / fmaxf(sqrtf(ss), 1e-12f);
    __nv_bfloat16* o = qn + (size_t)row * DIM;
    o[lane]      = __float2bfloat16(a * inv);
    o[lane + 32] = __float2bfloat16(b * inv);
}

// ---------------------------------------------------------------------------
// Prep 2: transpose + convert: x[bh][n][d] fp32 -> vt[bh][d][n] bf16
// ---------------------------------------------------------------------------
__global__ void transpose_bf16_kernel(const float* __restrict__ x, __nv_bfloat16* __restrict__ vt) {
    __shared__ float tile[64][65];
    int bh = blockIdx.y;
    int n0 = blockIdx.x * 64;
    const float* xb = x + ((size_t)bh * NSEQ + n0) * DIM;
    #pragma unroll
    for (int i = 0; i < 16; i++) {
        int idx = threadIdx.x + i * 256;
        int n = idx >> 6, d = idx & 63;
        tile[d][n] = xb[idx];
    }
    __syncthreads();
    __nv_bfloat16* vb = vt + (size_t)bh * NSEQ * DIM + n0;
    #pragma unroll
    for (int i = 0; i < 16; i++) {
        int idx = threadIdx.x + i * 256;
        int d = idx >> 6, n = idx & 63;
        vb[(size_t)d * NSEQ + n] = __float2bfloat16(tile[d][n]);
    }
}

// ---------------------------------------------------------------------------
// Flash-attention block on mma.sync (bf16 in, fp32 accum).
// Grid (NSEQ/128, BH), 256 threads / 8 warps. M=128 q rows, 16 per warp.
// Key tile = 64. Padded smem rows (72 bf16 = 144B) -> conflict-free LDS.32
// B-fragment loads. cp.async double buffering.
// ---------------------------------------------------------------------------
#define KV_STRIDE 72          // bf16 elements per smem row (144 bytes)
#define TILE_BYTES 9216       // 64 * 144
#define BUF_BYTES (2 * TILE_BYTES)
#define AV_STRIDE 34          // u32 per row (68 bf16)
#define W_SM_OFF 17408        // 128*34*4 bytes of av, then W (16KB)

__global__ void __launch_bounds__(256, 2)
attn_mma_kernel(const float* __restrict__ x,
                const __nv_bfloat16* __restrict__ qk,
                const __nv_bfloat16* __restrict__ vt,
                const float* __restrict__ W,
                const float* __restrict__ alpha_p,
                float* __restrict__ out) {
    __shared__ __align__(16) uint8_t smem_raw[36864];

    const int tid  = threadIdx.x;
    const int warp = tid >> 5;
    const int lane = tid & 31;
    const int lr   = lane >> 2;       // fragment row (0..7)
    const int lc   = lane & 3;        // fragment col group (0..3)
    const uint32_t smbase = smem_u32(smem_raw);

    const size_t base = (size_t)blockIdx.y * NSEQ * DIM;
    const int q0 = blockIdx.x * 128 + warp * 16;   // first q row of this warp
    const float scale = 1.0f / fmaxf(alpha_p[0], 0.01f);

    // ---- Q A-fragments (16 regs, held whole kernel) ----
    uint32_t aQ[4][4];
    {
        const __nv_bfloat16* qr0 = qk + base + (size_t)(q0 + lr) * DIM;
        const __nv_bfloat16* qr1 = qr0 + 8 * DIM;
        #pragma unroll
        for (int j = 0; j < 4; j++) {
            aQ[j][0] = *(const uint32_t*)(qr0 + 16 * j + 2 * lc);
            aQ[j][1] = *(const uint32_t*)(qr1 + 16 * j + 2 * lc);
            aQ[j][2] = *(const uint32_t*)(qr0 + 16 * j + 8 + 2 * lc);
            aQ[j][3] = *(const uint32_t*)(qr1 + 16 * j + 8 + 2 * lc);
        }
    }

    const __nv_bfloat16* gK  = qk + base;   // [key][d]
    const __nv_bfloat16* gVt = vt + base;   // [d][key]

    // ---- stage tile 0 ----
    {
        #pragma unroll
        for (int i = 0; i < 2; i++) {
            int id = tid + i * 256;
            int n = id >> 3, c = id & 7;
            uint32_t dst = smbase + n * 144 + c * 16;
            CP_ASYNC16(dst, gK + n * DIM + c * 8);
            CP_ASYNC16(dst + TILE_BYTES, gVt + (size_t)n * NSEQ + c * 8);
        }
        CP_COMMIT();
    }

    float o[8][4];
    #pragma unroll
    for (int b = 0; b < 8; b++)
        #pragma unroll
        for (int k = 0; k < 4; k++) o[b][k] = 0.0f;
    float l0 = 0.0f, l1 = 0.0f;

    const uint32_t offn = lr * 144 + lc * 4;   // per-lane B-frag offset

    for (int it = 0; it < NSEQ / 64; ++it) {
        CP_WAIT0();
        __syncthreads();
        const uint32_t smK = smbase + (uint32_t)(it & 1) * BUF_BYTES;
        const uint32_t smV = smK + TILE_BYTES;

        // prefetch next tile into other buffer
        if (it + 1 < NSEQ / 64) {
            const __nv_bfloat16* nK  = gK  + (it + 1) * 64 * DIM;
            const __nv_bfloat16* nVt = gVt + (it + 1) * 64;
            uint32_t dbuf = smbase + (uint32_t)((it + 1) & 1) * BUF_BYTES;
            #pragma unroll
            for (int i = 0; i < 2; i++) {
                int id = tid + i * 256;
                int n = id >> 3, c = id & 7;
                uint32_t dst = dbuf + n * 144 + c * 16;
                CP_ASYNC16(dst, nK + n * DIM + c * 8);
                CP_ASYNC16(dst + TILE_BYTES, nVt + (size_t)n * NSEQ + c * 8);
            }
            CP_COMMIT();
        }

        // ---- S = Q @ K^T  (16 x 64 per warp) ----
        float s[8][4];
        #pragma unroll
        for (int b = 0; b < 8; b++) {
            s[b][0] = s[b][1] = s[b][2] = s[b][3] = 0.0f;
            uint32_t abase = smK + b * (8 * 144) + offn;
            #pragma unroll
            for (int j = 0; j < 4; j++) {
                uint32_t b0 = lds32(abase + j * 32);
                uint32_t b1 = lds32(abase + j * 32 + 16);
                mma_bf16(s[b], aQ[j], b0, b1);
            }
        }

        // ---- softmax: p = exp(scale*(s-1)); pack into P A-fragments ----
        uint32_t aP[4][4];
        #pragma unroll
        for (int b = 0; b < 8; b++) {
            float e0 = __expf(fmaf(s[b][0], scale, -scale));
            float e1 = __expf(fmaf(s[b][1], scale, -scale));
            float e2 = __expf(fmaf(s[b][2], scale, -scale));
            float e3 = __expf(fmaf(s[b][3], scale, -scale));
            l0 += e0 + e1;
            l1 += e2 + e3;
            int j = b >> 1;
            if ((b & 1) == 0) {
                aP[j][0] = packbf(e0, e1);
                aP[j][1] = packbf(e2, e3);
            } else {
                aP[j][2] = packbf(e0, e1);
                aP[j][3] = packbf(e2, e3);
            }
        }

        // ---- O += P @ V  (B-frags from Vt[d][key]) ----
        #pragma unroll
        for (int b = 0; b < 8; b++) {
            uint32_t abase = smV + b * (8 * 144) + offn;
            #pragma unroll
            for (int j = 0; j < 4; j++) {
                uint32_t b0 = lds32(abase + j * 32);
                uint32_t b1 = lds32(abase + j * 32 + 16);
                mma_bf16(o[b], aP[j], b0, b1);
            }
        }
    }

    // ---- row sums across quad; normalize; av -> smem (bf16) ----
    l0 += __shfl_xor_sync(0xFFFFFFFFu, l0, 1);
    l0 += __shfl_xor_sync(0xFFFFFFFFu, l0, 2);
    l1 += __shfl_xor_sync(0xFFFFFFFFu, l1, 1);
    l1 += __shfl_xor_sync(0xFFFFFFFFu, l1, 2);
    const float invl0 = 1.0f / l0;
    const float invl1 = 1.0f / l1;

    __syncthreads();   // all warps done with K/V smem

    {
        int row0 = warp * 16 + lr;
        uint32_t a0 = smbase + (uint32_t)(row0 * AV_STRIDE + lc) * 4;
        uint32_t a1 = smbase + (uint32_t)((row0 + 8) * AV_STRIDE + lc) * 4;
        #pragma unroll
        for (int b = 0; b < 8; b++) {
            sts32(a0 + b * 16, packbf(o[b][0] * invl0, o[b][1] * invl0));
            sts32(a1 + b * 16, packbf(o[b][2] * invl1, o[b][3] * invl1));
        }
    }
    // stage W (64x64 f32 = 16KB) after av region
    {
        #pragma unroll
        for (int i = 0; i < 4; i++) {
            int idx = tid + i * 256;
            CP_ASYNC16(smbase + W_SM_OFF + idx * 16, (const float4*)W + idx);
        }
        CP_COMMIT();
        CP_WAIT0();
    }
    __syncthreads();

    // ---- epilogue: y = relu(av @ W^T + x) ----
    {
        const int rowc = warp * 16 + (lane >> 1);   // row in CTA
        const int half = lane & 1;                  // e half: 0..31 / 32..63
        // load av row (64 bf16) -> fp32
        float avf[64];
        uint32_t abase = smbase + (uint32_t)(rowc * AV_STRIDE) * 4;
        #pragma unroll
        for (int i = 0; i < 32; i++) {
            uint32_t u = lds32(abase + i * 4);
            __nv_bfloat162 h = *reinterpret_cast<__nv_bfloat162*>(&u);
            float2 f = __bfloat1622float2(h);
            avf[2 * i] = f.x;
            avf[2 * i + 1] = f.y;
        }
        const int grow = blockIdx.x * 128 + rowc;
        const float4* xr4 = (const float4*)(x + base + (size_t)grow * DIM) + half * 8;
        float4* out4 = (float4*)(out + base + (size_t)grow * DIM) + half * 8;
        #pragma unroll 1
        for (int eb = 0; eb < 8; eb++) {
            float r[4];
            #pragma unroll
            for (int k = 0; k < 4; k++) {
                int e = half * 32 + eb * 4 + k;
                uint32_t wbase = smbase + W_SM_OFF + (uint32_t)e * 256;
                float4 acc = make_float4(0.f, 0.f, 0.f, 0.f);
                #pragma unroll
                for (int i = 0; i < 16; i++) {
                    float4 wv = lds128(wbase + i * 16);
                    acc.x = fmaf(avf[4 * i + 0], wv.x, acc.x);
                    acc.y = fmaf(avf[4 * i + 1], wv.y, acc.y);
                    acc.z = fmaf(avf[4 * i + 2], wv.z, acc.z);
                    acc.w = fmaf(avf[4 * i + 3], wv.w, acc.w);
                }
                r[k] = (acc.x + acc.y) + (acc.z + acc.w);
            }
            float4 xr = xr4[eb];
            float4 res;
            res.x = fmaxf(r[0] + xr.x, 0.0f);
            res.y = fmaxf(r[1] + xr.y, 0.0f);
            res.z = fmaxf(r[2] + xr.z, 0.0f);
            res.w = fmaxf(r[3] + xr.w, 0.0f);
            out4[eb] = res;
        }
    }
}

// ---------------------------------------------------------------------------
// Driver (graph-capturable)
// ---------------------------------------------------------------------------
extern "C" void kernel_launch(void* const* d_in, const int* in_sizes, int n_in,
                              void* d_out, int out_size) {
    const float* x      = (const float*)d_in[0];
    const float* W1     = (const float*)d_in[1];
    const float* W2     = (const float*)d_in[2];
    const float* alpha1 = (const float*)d_in[3];
    const float* alpha2 = (const float*)d_in[4];
    float* out = (float*)d_out;

    __nv_bfloat16* qk;  cudaGetSymbolAddress((void**)&qk,  g_qk);
    __nv_bfloat16* vtp; cudaGetSymbolAddress((void**)&vtp, g_vt);
    float* tmp;         cudaGetSymbolAddress((void**)&tmp, g_tmp);

    dim3 ngrid((ROWS * 32 + 127) / 128);
    dim3 tgrid(NSEQ / 64, BH);
    dim3 agrid(NSEQ / 128, BH);

    // Block 1
    norm_bf16_kernel<<<ngrid, 128>>>(x, qk);
    transpose_bf16_kernel<<<tgrid, 256>>>(x, vtp);
    attn_mma_kernel<<<agrid, 256>>>(x, qk, vtp, W1, alpha1, tmp);
    // Block 2
    norm_bf16_kernel<<<ngrid, 128>>>(tmp, qk);
    transpose_bf16_kernel<<<tgrid, 256>>>(tmp, vtp);
    attn_mma_kernel<<<agrid, 256>>>(tmp, qk, vtp, W2, alpha2, out);
}

// round 4
// speedup vs baseline: 9.0419x; 1.0331x over previous
#include <cuda_runtime.h>
#include <cuda_bf16.h>
#include <cstdint>

#define BH   16
#define NSEQ 4096
#define DIM  64
#define ROWS (BH * NSEQ)
#define ELEMS (ROWS * DIM)

// Scratch (__device__ globals per allocation-free rule)
__device__ __nv_bfloat16 g_qk[ELEMS];   // normalized x, bf16, [bh][n][d]
__device__ __nv_bfloat16 g_vt[ELEMS];   // x transposed,  bf16, [bh][d][n]
__device__ float         g_tmp[ELEMS];  // block-1 output

// ---------------------------------------------------------------------------
// helpers
// ---------------------------------------------------------------------------
__device__ __forceinline__ uint32_t smem_u32(const void* p) {
    uint32_t a;
    asm("{ .reg .u64 t; cvta.to.shared.u64 t, %1; cvt.u32.u64 %0, t; }" : "=r"(a) : "l"(p));
    return a;
}
__device__ __forceinline__ uint32_t lds32(uint32_t a) {
    uint32_t v;
    asm volatile("ld.shared.b32 %0, [%1];" : "=r"(v) : "r"(a));
    return v;
}
__device__ __forceinline__ void sts32(uint32_t a, uint32_t v) {
    asm volatile("st.shared.b32 [%0], %1;" :: "r"(a), "r"(v));
}
__device__ __forceinline__ float4 lds128(uint32_t a) {
    float4 v;
    asm volatile("ld.shared.v4.f32 {%0,%1,%2,%3}, [%4];"
                 : "=f"(v.x), "=f"(v.y), "=f"(v.z), "=f"(v.w) : "r"(a));
    return v;
}
__device__ __forceinline__ void ldsm_x4(uint32_t r[4], uint32_t addr) {
    asm volatile("ldmatrix.sync.aligned.m8n8.x4.shared.b16 {%0,%1,%2,%3}, [%4];"
                 : "=r"(r[0]), "=r"(r[1]), "=r"(r[2]), "=r"(r[3]) : "r"(addr));
}
__device__ __forceinline__ uint32_t packbf(float lo, float hi) {
    uint32_t r;
    asm("cvt.rn.satfinite.bf16x2.f32 %0, %1, %2;" : "=r"(r) : "f"(hi), "f"(lo));
    return r;
}
// p = 2^y for a bf16x2 pair built from two fp32 y values
__device__ __forceinline__ uint32_t exp2_bf16x2(float y0, float y1) {
    uint32_t h = packbf(y0, y1);
    uint32_t r;
    asm("ex2.approx.ftz.bf16x2 %0, %1;" : "=r"(r) : "r"(h));
    return r;
}
__device__ __forceinline__ void mma_bf16(float c[4], const uint32_t a[4],
                                         uint32_t b0, uint32_t b1) {
    asm("mma.sync.aligned.m16n8k16.row.col.f32.bf16.bf16.f32 "
        "{%0,%1,%2,%3},{%4,%5,%6,%7},{%8,%9},{%0,%1,%2,%3};"
        : "+f"(c[0]), "+f"(c[1]), "+f"(c[2]), "+f"(c[3])
        : "r"(a[0]), "r"(a[1]), "r"(a[2]), "r"(a[3]), "r"(b0), "r"(b1));
}
#define CP_ASYNC16(dst, src) \
    asm volatile("cp.async.cg.shared.global [%0], [%1], 16;" :: "r"(dst), "l"(src))
#define CP_COMMIT() asm volatile("cp.async.commit_group;" ::: "memory")
#define CP_WAIT0()  asm volatile("cp.async.wait_group 0;" ::: "memory")

// ---------------------------------------------------------------------------
// Fused prep: per 64-row tile, L2-normalize rows -> qn (bf16 [n][d]) and
// transpose -> vt (bf16 [d][n]). Reads x once.
// ---------------------------------------------------------------------------
__global__ void __launch_bounds__(256)
prep_kernel(const float* __restrict__ x,
            __nv_bfloat16* __restrict__ qn, __nv_bfloat16* __restrict__ vt) {
    __shared__ float tile[64][65];
    __shared__ float sinv[64];
    const int tid = threadIdx.x;
    const int bh = blockIdx.y;
    const int n0 = blockIdx.x * 64;
    const float* xb = x + ((size_t)bh * NSEQ + n0) * DIM;
    #pragma unroll
    for (int i = 0; i < 16; i++) {
        int idx = tid + i * 256;
        tile[idx >> 6][idx & 63] = xb[idx];
    }
    __syncthreads();
    {
        int n = tid >> 2, p = tid & 3;
        float ss = 0.0f;
        #pragma unroll
        for (int k = 0; k < 16; k++) {
            float v = tile[n][p * 16 + k];
            ss = fmaf(v, v, ss);
        }
        ss += __shfl_xor_sync(0xFFFFFFFFu, ss, 1);
        ss += __shfl_xor_sync(0xFFFFFFFFu, ss, 2);
        if (p == 0) sinv[n] = 1.0f / fmaxf(sqrtf(ss), 1e-12f);
    }
    __syncthreads();
    __nv_bfloat16* qb = qn + ((size_t)bh * NSEQ + n0) * DIM;
    __nv_bfloat16* vb = vt + (size_t)bh * NSEQ * DIM + n0;
    #pragma unroll
    for (int i = 0; i < 16; i++) {
        int idx = tid + i * 256;
        int n = idx >> 6, d = idx & 63;
        qb[idx] = __float2bfloat16(tile[n][d] * sinv[n]);
    }
    #pragma unroll
    for (int i = 0; i < 16; i++) {
        int idx = tid + i * 256;
        int d = idx >> 6, n = idx & 63;
        vb[(size_t)d * NSEQ + n] = __float2bfloat16(tile[n][d]);
    }
}

// ---------------------------------------------------------------------------
// Flash-attention block on mma.sync (bf16, fp32 accum).
// 256 threads / 8 warps, M=128 q rows (16/warp), 64-key tiles, double buffer.
// ldmatrix.x4 B-fragments; softmax via ex2.approx.bf16x2 (1 MUFU / 2 scores);
// row-sum l via a ones-column in the V tile (extra 8-wide d block).
// smem tile rows padded to 144B (conflict-free LDSM).
// ---------------------------------------------------------------------------
#define KV_ROWB 144
#define KT_BYTES (64 * KV_ROWB)        // 9216
#define VT_BYTES (72 * KV_ROWB)        // 10368 (64 data rows + ones row + pad)
#define BUF_BYTES (KT_BYTES + VT_BYTES) // 19584
#define AV_STRIDE 34                    // u32 per row (68 bf16)
#define W_SM_OFF 17408                  // av: 128*34*4 bytes, then W (16KB)

__global__ void __launch_bounds__(256, 2)
attn_mma_kernel(const float* __restrict__ x,
                const __nv_bfloat16* __restrict__ qk,
                const __nv_bfloat16* __restrict__ vt,
                const float* __restrict__ W,
                const float* __restrict__ alpha_p,
                float* __restrict__ out) {
    __shared__ __align__(16) uint8_t smem_raw[2 * BUF_BYTES];

    const int tid  = threadIdx.x;
    const int warp = tid >> 5;
    const int lane = tid & 31;
    const int lr   = lane >> 2;
    const int lc   = lane & 3;
    const uint32_t smbase = smem_u32(smem_raw);

    const size_t base = (size_t)blockIdx.y * NSEQ * DIM;
    const int q0 = blockIdx.x * 128 + warp * 16;
    // fold log2e: p = 2^((s-1)*scale*log2e)
    const float c = 1.4426950408889634f / fmaxf(alpha_p[0], 0.01f);

    // ---- Q A-fragments ----
    uint32_t aQ[4][4];
    {
        const __nv_bfloat16* qr0 = qk + base + (size_t)(q0 + lr) * DIM;
        const __nv_bfloat16* qr1 = qr0 + 8 * DIM;
        #pragma unroll
        for (int j = 0; j < 4; j++) {
            aQ[j][0] = *(const uint32_t*)(qr0 + 16 * j + 2 * lc);
            aQ[j][1] = *(const uint32_t*)(qr1 + 16 * j + 2 * lc);
            aQ[j][2] = *(const uint32_t*)(qr0 + 16 * j + 8 + 2 * lc);
            aQ[j][3] = *(const uint32_t*)(qr1 + 16 * j + 8 + 2 * lc);
        }
    }

    const __nv_bfloat16* gK  = qk + base;   // [key][d]
    const __nv_bfloat16* gVt = vt + base;   // [d][key]

    // ---- init ones/zero rows (V rows 64..71) in BOTH buffers ----
    {
        #pragma unroll
        for (int i = 0; i < 2; i++) {
            int idx = tid + i * 256;
            if (idx < 288) {
                uint32_t v = (idx < 36) ? 0x3F803F80u : 0u;   // row 64 = 1.0 bf16
                sts32(smbase + KT_BYTES + 64 * KV_ROWB + idx * 4, v);
                sts32(smbase + BUF_BYTES + KT_BYTES + 64 * KV_ROWB + idx * 4, v);
            }
        }
    }

    // ---- stage tile 0 ----
    {
        #pragma unroll
        for (int i = 0; i < 2; i++) {
            int id = tid + i * 256;
            int n = id >> 3, cseg = id & 7;
            CP_ASYNC16(smbase + n * KV_ROWB + cseg * 16, gK + n * DIM + cseg * 8);
            CP_ASYNC16(smbase + KT_BYTES + n * KV_ROWB + cseg * 16,
                       gVt + (size_t)n * NSEQ + cseg * 8);
        }
        CP_COMMIT();
    }

    float o[9][4];
    #pragma unroll
    for (int b = 0; b < 9; b++)
        #pragma unroll
        for (int k = 0; k < 4; k++) o[b][k] = 0.0f;

    const uint32_t lrow = (uint32_t)(lane & 7) * KV_ROWB;
    const uint32_t kseg = (uint32_t)(lane >> 3) * 16;

    for (int it = 0; it < NSEQ / 64; ++it) {
        CP_WAIT0();
        __syncthreads();
        const uint32_t smK = smbase + (uint32_t)(it & 1) * BUF_BYTES;
        const uint32_t smV = smK + KT_BYTES;

        if (it + 1 < NSEQ / 64) {
            const __nv_bfloat16* nK  = gK  + (it + 1) * 64 * DIM;
            const __nv_bfloat16* nVt = gVt + (it + 1) * 64;
            uint32_t dbuf = smbase + (uint32_t)((it + 1) & 1) * BUF_BYTES;
            #pragma unroll
            for (int i = 0; i < 2; i++) {
                int id = tid + i * 256;
                int n = id >> 3, cseg = id & 7;
                CP_ASYNC16(dbuf + n * KV_ROWB + cseg * 16, nK + n * DIM + cseg * 8);
                CP_ASYNC16(dbuf + KT_BYTES + n * KV_ROWB + cseg * 16,
                           nVt + (size_t)n * NSEQ + cseg * 8);
            }
            CP_COMMIT();
        }

        // ---- S = Q@K^T per key-block b, softmax immediately -> aP ----
        uint32_t aP[4][4];
        #pragma unroll
        for (int b = 0; b < 8; b++) {
            float s[4];
            s[0] = s[1] = s[2] = s[3] = 0.0f;
            uint32_t abase = smK + (uint32_t)b * (8 * KV_ROWB) + lrow + kseg;
            uint32_t f0[4], f1[4];
            ldsm_x4(f0, abase);          // k 0..31  -> j0, j1
            ldsm_x4(f1, abase + 64);     // k 32..63 -> j2, j3
            mma_bf16(s, aQ[0], f0[0], f0[1]);
            mma_bf16(s, aQ[1], f0[2], f0[3]);
            mma_bf16(s, aQ[2], f1[0], f1[1]);
            mma_bf16(s, aQ[3], f1[2], f1[3]);
            // p = 2^(c*(s-1)), packed straight into A-fragment slots
            uint32_t pa = exp2_bf16x2(fmaf(s[0], c, -c), fmaf(s[1], c, -c));
            uint32_t pb = exp2_bf16x2(fmaf(s[2], c, -c), fmaf(s[3], c, -c));
            int j = b >> 1;
            if ((b & 1) == 0) { aP[j][0] = pa; aP[j][1] = pb; }
            else              { aP[j][2] = pa; aP[j][3] = pb; }
        }

        // ---- O += P @ [V ; ones] (9 d-blocks; block 8 col 64 = row-sum l) ----
        #pragma unroll
        for (int b = 0; b < 9; b++) {
            uint32_t abase = smV + (uint32_t)b * (8 * KV_ROWB) + lrow + kseg;
            uint32_t f0[4], f1[4];
            ldsm_x4(f0, abase);
            ldsm_x4(f1, abase + 64);
            mma_bf16(o[b], aP[0], f0[0], f0[1]);
            mma_bf16(o[b], aP[1], f0[2], f0[3]);
            mma_bf16(o[b], aP[2], f1[0], f1[1]);
            mma_bf16(o[b], aP[3], f1[2], f1[3]);
        }
    }

    // ---- l = ones-column accumulator (d=64 -> lc==0, regs 0/2), broadcast ----
    const float lA = __shfl_sync(0xFFFFFFFFu, o[8][0], lane & ~3);
    const float lB = __shfl_sync(0xFFFFFFFFu, o[8][2], lane & ~3);
    const float invl0 = 1.0f / lA;
    const float invl1 = 1.0f / lB;

    __syncthreads();   // all warps done with K/V smem

    // ---- av -> smem (bf16 rows) ----
    {
        int row0 = warp * 16 + lr;
        uint32_t a0 = smbase + (uint32_t)(row0 * AV_STRIDE + lc) * 4;
        uint32_t a1 = smbase + (uint32_t)((row0 + 8) * AV_STRIDE + lc) * 4;
        #pragma unroll
        for (int b = 0; b < 8; b++) {
            sts32(a0 + b * 16, packbf(o[b][0] * invl0, o[b][1] * invl0));
            sts32(a1 + b * 16, packbf(o[b][2] * invl1, o[b][3] * invl1));
        }
    }
    // stage W (64x64 f32 = 16KB)
    {
        #pragma unroll
        for (int i = 0; i < 4; i++) {
            int idx = tid + i * 256;
            CP_ASYNC16(smbase + W_SM_OFF + idx * 16, (const float4*)W + idx);
        }
        CP_COMMIT();
        CP_WAIT0();
    }
    __syncthreads();

    // ---- epilogue: y = relu(av @ W^T + x) ----
    {
        const int rowc = warp * 16 + (lane >> 1);
        const int half = lane & 1;
        float avf[64];
        uint32_t abase = smbase + (uint32_t)(rowc * AV_STRIDE) * 4;
        #pragma unroll
        for (int i = 0; i < 32; i++) {
            uint32_t u = lds32(abase + i * 4);
            __nv_bfloat162 h = *reinterpret_cast<__nv_bfloat162*>(&u);
            float2 f = __bfloat1622float2(h);
            avf[2 * i] = f.x;
            avf[2 * i + 1] = f.y;
        }
        const int grow = blockIdx.x * 128 + rowc;
        const float4* xr4 = (const float4*)(x + base + (size_t)grow * DIM) + half * 8;
        float4* out4 = (float4*)(out + base + (size_t)grow * DIM) + half * 8;
        #pragma unroll 1
        for (int eb = 0; eb < 8; eb++) {
            float r[4];
            #pragma unroll
            for (int k = 0; k < 4; k++) {
                int e = half * 32 + eb * 4 + k;
                uint32_t wbase = smbase + W_SM_OFF + (uint32_t)e * 256;
                float4 acc = make_float4(0.f, 0.f, 0.f, 0.f);
                #pragma unroll
                for (int i = 0; i < 16; i++) {
                    float4 wv = lds128(wbase + i * 16);
                    acc.x = fmaf(avf[4 * i + 0], wv.x, acc.x);
                    acc.y = fmaf(avf[4 * i + 1], wv.y, acc.y);
                    acc.z = fmaf(avf[4 * i + 2], wv.z, acc.z);
                    acc.w = fmaf(avf[4 * i + 3], wv.w, acc.w);
                }
                r[k] = (acc.x + acc.y) + (acc.z + acc.w);
            }
            float4 xr = xr4[eb];
            float4 res;
            res.x = fmaxf(r[0] + xr.x, 0.0f);
            res.y = fmaxf(r[1] + xr.y, 0.0f);
            res.z = fmaxf(r[2] + xr.z, 0.0f);
            res.w = fmaxf(r[3] + xr.w, 0.0f);
            out4[eb] = res;
        }
    }
}

// ---------------------------------------------------------------------------
// Driver (graph-capturable)
// ---------------------------------------------------------------------------
extern "C" void kernel_launch(void* const* d_in, const int* in_sizes, int n_in,
                              void* d_out, int out_size) {
    const float* x      = (const float*)d_in[0];
    const float* W1     = (const float*)d_in[1];
    const float* W2     = (const float*)d_in[2];
    const float* alpha1 = (const float*)d_in[3];
    const float* alpha2 = (const float*)d_in[4];
    float* out = (float*)d_out;

    __nv_bfloat16* qk;  cudaGetSymbolAddress((void**)&qk,  g_qk);
    __nv_bfloat16* vtp; cudaGetSymbolAddress((void**)&vtp, g_vt);
    float* tmp;         cudaGetSymbolAddress((void**)&tmp, g_tmp);

    dim3 pgrid(NSEQ / 64, BH);
    dim3 agrid(NSEQ / 128, BH);

    prep_kernel<<<pgrid, 256>>>(x, qk, vtp);
    attn_mma_kernel<<<agrid, 256>>>(x, qk, vtp, W1, alpha1, tmp);
    prep_kernel<<<pgrid, 256>>>(tmp, qk, vtp);
    attn_mma_kernel<<<agrid, 256>>>(tmp, qk, vtp, W2, alpha2, out);
}

// round 5
// speedup vs baseline: 11.6965x; 1.2936x over previous
#include <cuda_runtime.h>
#include <cuda_bf16.h>
#include <cstdint>

#define BH   16
#define NSEQ 4096
#define DIM  64
#define ROWS (BH * NSEQ)
#define ELEMS (ROWS * DIM)

// Scratch (__device__ globals per allocation-free rule)
__device__ __nv_bfloat16 g_qk[ELEMS];   // normalized x, bf16, [bh][n][d]
__device__ __nv_bfloat16 g_vt[ELEMS];   // x transposed,  bf16, [bh][d][n]
__device__ float         g_tmp[ELEMS];  // block-1 output

// ---------------------------------------------------------------------------
// helpers
// ---------------------------------------------------------------------------
__device__ __forceinline__ uint32_t smem_u32(const void* p) {
    uint32_t a;
    asm("{ .reg .u64 t; cvta.to.shared.u64 t, %1; cvt.u32.u64 %0, t; }" : "=r"(a) : "l"(p));
    return a;
}
__device__ __forceinline__ uint32_t lds32(uint32_t a) {
    uint32_t v;
    asm volatile("ld.shared.b32 %0, [%1];" : "=r"(v) : "r"(a));
    return v;
}
__device__ __forceinline__ void sts32(uint32_t a, uint32_t v) {
    asm volatile("st.shared.b32 [%0], %1;" :: "r"(a), "r"(v));
}
__device__ __forceinline__ float4 lds128(uint32_t a) {
    float4 v;
    asm volatile("ld.shared.v4.f32 {%0,%1,%2,%3}, [%4];"
                 : "=f"(v.x), "=f"(v.y), "=f"(v.z), "=f"(v.w) : "r"(a));
    return v;
}
__device__ __forceinline__ void ldsm_x4(uint32_t r[4], uint32_t addr) {
    asm volatile("ldmatrix.sync.aligned.m8n8.x4.shared.b16 {%0,%1,%2,%3}, [%4];"
                 : "=r"(r[0]), "=r"(r[1]), "=r"(r[2]), "=r"(r[3]) : "r"(addr));
}
__device__ __forceinline__ uint32_t packbf(float lo, float hi) {
    uint32_t r;
    asm("cvt.rn.satfinite.bf16x2.f32 %0, %1, %2;" : "=r"(r) : "f"(hi), "f"(lo));
    return r;
}
__device__ __forceinline__ uint32_t exp2_bf16x2(float y0, float y1) {
    uint32_t h = packbf(y0, y1);
    uint32_t r;
    asm("ex2.approx.ftz.bf16x2 %0, %1;" : "=r"(r) : "r"(h));
    return r;
}
__device__ __forceinline__ void mma_bf16(float c[4], const uint32_t a[4],
                                         uint32_t b0, uint32_t b1) {
    asm("mma.sync.aligned.m16n8k16.row.col.f32.bf16.bf16.f32 "
        "{%0,%1,%2,%3},{%4,%5,%6,%7},{%8,%9},{%0,%1,%2,%3};"
        : "+f"(c[0]), "+f"(c[1]), "+f"(c[2]), "+f"(c[3])
        : "r"(a[0]), "r"(a[1]), "r"(a[2]), "r"(a[3]), "r"(b0), "r"(b1));
}
#define CP_ASYNC16(dst, src) \
    asm volatile("cp.async.cg.shared.global [%0], [%1], 16;" :: "r"(dst), "l"(src))
#define CP_COMMIT() asm volatile("cp.async.commit_group;" ::: "memory")
#define CP_WAIT0()  asm volatile("cp.async.wait_group 0;" ::: "memory")

// ---------------------------------------------------------------------------
// Fused prep: L2-normalize rows -> qn (bf16 [n][d]); transpose -> vt ([d][n])
// ---------------------------------------------------------------------------
__global__ void __launch_bounds__(256)
prep_kernel(const float* __restrict__ x,
            __nv_bfloat16* __restrict__ qn, __nv_bfloat16* __restrict__ vt) {
    __shared__ float tile[64][65];
    __shared__ float sinv[64];
    const int tid = threadIdx.x;
    const int bh = blockIdx.y;
    const int n0 = blockIdx.x * 64;
    const float* xb = x + ((size_t)bh * NSEQ + n0) * DIM;
    #pragma unroll
    for (int i = 0; i < 16; i++) {
        int idx = tid + i * 256;
        tile[idx >> 6][idx & 63] = xb[idx];
    }
    __syncthreads();
    {
        int n = tid >> 2, p = tid & 3;
        float ss = 0.0f;
        #pragma unroll
        for (int k = 0; k < 16; k++) {
            float v = tile[n][p * 16 + k];
            ss = fmaf(v, v, ss);
        }
        ss += __shfl_xor_sync(0xFFFFFFFFu, ss, 1);
        ss += __shfl_xor_sync(0xFFFFFFFFu, ss, 2);
        if (p == 0) sinv[n] = 1.0f / fmaxf(sqrtf(ss), 1e-12f);
    }
    __syncthreads();
    __nv_bfloat16* qb = qn + ((size_t)bh * NSEQ + n0) * DIM;
    __nv_bfloat16* vb = vt + (size_t)bh * NSEQ * DIM + n0;
    #pragma unroll
    for (int i = 0; i < 16; i++) {
        int idx = tid + i * 256;
        int n = idx >> 6, d = idx & 63;
        qb[idx] = __float2bfloat16(tile[n][d] * sinv[n]);
    }
    #pragma unroll
    for (int i = 0; i < 16; i++) {
        int idx = tid + i * 256;
        int d = idx >> 6, n = idx & 63;
        vb[(size_t)d * NSEQ + n] = __float2bfloat16(tile[n][d]);
    }
}

// ---------------------------------------------------------------------------
// Flash-attention block on mma.sync.
// 128 threads / 4 warps, M=128 (32 q rows per warp = 2 row-groups) -> each
// ldmatrix B-fragment feeds 8 MMAs (halves smem fragment traffic vs 16/warp).
// 64-key tiles, double-buffered cp.async; softmax via ex2.approx.bf16x2;
// row-sum l via ones-column in V tile. Rows padded to 144B.
// ---------------------------------------------------------------------------
#define KV_ROWB 144
#define KT_BYTES (64 * KV_ROWB)         // 9216
#define VT_BYTES (72 * KV_ROWB)         // 10368
#define BUF_BYTES (KT_BYTES + VT_BYTES) // 19584
#define AV_STRIDE 34                     // u32 per row (68 bf16)
#define W_SM_OFF 17408                   // av: 128*34*4, then W (16KB)

__global__ void __launch_bounds__(128, 2)
attn_mma_kernel(const float* __restrict__ x,
                const __nv_bfloat16* __restrict__ qk,
                const __nv_bfloat16* __restrict__ vt,
                const float* __restrict__ W,
                const float* __restrict__ alpha_p,
                float* __restrict__ out) {
    __shared__ __align__(16) uint8_t smem_raw[2 * BUF_BYTES];

    const int tid  = threadIdx.x;
    const int warp = tid >> 5;
    const int lane = tid & 31;
    const int lr   = lane >> 2;
    const int lc   = lane & 3;
    const uint32_t smbase = smem_u32(smem_raw);

    const size_t base = (size_t)blockIdx.y * NSEQ * DIM;
    const int q0 = blockIdx.x * 128 + warp * 32;
    const float c = 1.4426950408889634f / fmaxf(alpha_p[0], 0.01f);

    // ---- Q A-fragments: 2 row-groups x 4 k-chunks ----
    uint32_t aQ[2][4][4];
    #pragma unroll
    for (int rg = 0; rg < 2; rg++) {
        const __nv_bfloat16* qr0 = qk + base + (size_t)(q0 + rg * 16 + lr) * DIM;
        const __nv_bfloat16* qr1 = qr0 + 8 * DIM;
        #pragma unroll
        for (int j = 0; j < 4; j++) {
            aQ[rg][j][0] = *(const uint32_t*)(qr0 + 16 * j + 2 * lc);
            aQ[rg][j][1] = *(const uint32_t*)(qr1 + 16 * j + 2 * lc);
            aQ[rg][j][2] = *(const uint32_t*)(qr0 + 16 * j + 8 + 2 * lc);
            aQ[rg][j][3] = *(const uint32_t*)(qr1 + 16 * j + 8 + 2 * lc);
        }
    }

    const __nv_bfloat16* gK  = qk + base;
    const __nv_bfloat16* gVt = vt + base;

    // ---- init ones/zero rows (V rows 64..71) in BOTH buffers ----
    #pragma unroll
    for (int i = 0; i < 3; i++) {
        int idx = tid + i * 128;
        if (idx < 288) {
            uint32_t v = (idx < 36) ? 0x3F803F80u : 0u;
            sts32(smbase + KT_BYTES + 64 * KV_ROWB + idx * 4, v);
            sts32(smbase + BUF_BYTES + KT_BYTES + 64 * KV_ROWB + idx * 4, v);
        }
    }

    // ---- stage tile 0 ----
    #pragma unroll
    for (int i = 0; i < 4; i++) {
        int id = tid + i * 128;
        int n = id >> 3, cseg = id & 7;
        CP_ASYNC16(smbase + n * KV_ROWB + cseg * 16, gK + n * DIM + cseg * 8);
        CP_ASYNC16(smbase + KT_BYTES + n * KV_ROWB + cseg * 16,
                   gVt + (size_t)n * NSEQ + cseg * 8);
    }
    CP_COMMIT();

    float o[2][9][4];
    #pragma unroll
    for (int rg = 0; rg < 2; rg++)
        #pragma unroll
        for (int b = 0; b < 9; b++)
            #pragma unroll
            for (int k = 0; k < 4; k++) o[rg][b][k] = 0.0f;

    const uint32_t lrow = (uint32_t)(lane & 7) * KV_ROWB;
    const uint32_t kseg = (uint32_t)(lane >> 3) * 16;

    for (int it = 0; it < NSEQ / 64; ++it) {
        CP_WAIT0();
        __syncthreads();
        const uint32_t smK = smbase + (uint32_t)(it & 1) * BUF_BYTES;
        const uint32_t smV = smK + KT_BYTES;

        if (it + 1 < NSEQ / 64) {
            const __nv_bfloat16* nK  = gK  + (it + 1) * 64 * DIM;
            const __nv_bfloat16* nVt = gVt + (it + 1) * 64;
            uint32_t dbuf = smbase + (uint32_t)((it + 1) & 1) * BUF_BYTES;
            #pragma unroll
            for (int i = 0; i < 4; i++) {
                int id = tid + i * 128;
                int n = id >> 3, cseg = id & 7;
                CP_ASYNC16(dbuf + n * KV_ROWB + cseg * 16, nK + n * DIM + cseg * 8);
                CP_ASYNC16(dbuf + KT_BYTES + n * KV_ROWB + cseg * 16,
                           nVt + (size_t)n * NSEQ + cseg * 8);
            }
            CP_COMMIT();
        }

        // ---- S = Q@K^T per key-block; softmax -> aP (both row groups) ----
        uint32_t aP[2][4][4];
        #pragma unroll
        for (int b = 0; b < 8; b++) {
            uint32_t abase = smK + (uint32_t)b * (8 * KV_ROWB) + lrow + kseg;
            uint32_t f0[4], f1[4];
            ldsm_x4(f0, abase);
            ldsm_x4(f1, abase + 64);
            #pragma unroll
            for (int rg = 0; rg < 2; rg++) {
                float s[4];
                s[0] = s[1] = s[2] = s[3] = 0.0f;
                mma_bf16(s, aQ[rg][0], f0[0], f0[1]);
                mma_bf16(s, aQ[rg][1], f0[2], f0[3]);
                mma_bf16(s, aQ[rg][2], f1[0], f1[1]);
                mma_bf16(s, aQ[rg][3], f1[2], f1[3]);
                uint32_t pa = exp2_bf16x2(fmaf(s[0], c, -c), fmaf(s[1], c, -c));
                uint32_t pb = exp2_bf16x2(fmaf(s[2], c, -c), fmaf(s[3], c, -c));
                int j = b >> 1;
                if ((b & 1) == 0) { aP[rg][j][0] = pa; aP[rg][j][1] = pb; }
                else              { aP[rg][j][2] = pa; aP[rg][j][3] = pb; }
            }
        }

        // ---- O += P @ [V ; ones] ----
        #pragma unroll
        for (int b = 0; b < 9; b++) {
            uint32_t abase = smV + (uint32_t)b * (8 * KV_ROWB) + lrow + kseg;
            uint32_t f0[4], f1[4];
            ldsm_x4(f0, abase);
            ldsm_x4(f1, abase + 64);
            #pragma unroll
            for (int rg = 0; rg < 2; rg++) {
                mma_bf16(o[rg][b], aP[rg][0], f0[0], f0[1]);
                mma_bf16(o[rg][b], aP[rg][1], f0[2], f0[3]);
                mma_bf16(o[rg][b], aP[rg][2], f1[0], f1[1]);
                mma_bf16(o[rg][b], aP[rg][3], f1[2], f1[3]);
            }
        }
    }

    __syncthreads();   // all warps done with K/V smem

    // ---- normalize by l (ones-column, d=64 -> lc==0 regs 0/2), av -> smem ----
    #pragma unroll
    for (int rg = 0; rg < 2; rg++) {
        const float lA = __shfl_sync(0xFFFFFFFFu, o[rg][8][0], lane & ~3);
        const float lB = __shfl_sync(0xFFFFFFFFu, o[rg][8][2], lane & ~3);
        const float invl0 = 1.0f / lA;
        const float invl1 = 1.0f / lB;
        int row0 = warp * 32 + rg * 16 + lr;
        uint32_t a0 = smbase + (uint32_t)(row0 * AV_STRIDE + lc) * 4;
        uint32_t a1 = smbase + (uint32_t)((row0 + 8) * AV_STRIDE + lc) * 4;
        #pragma unroll
        for (int b = 0; b < 8; b++) {
            sts32(a0 + b * 16, packbf(o[rg][b][0] * invl0, o[rg][b][1] * invl0));
            sts32(a1 + b * 16, packbf(o[rg][b][2] * invl1, o[rg][b][3] * invl1));
        }
    }
    // stage W (64x64 f32 = 16KB)
    #pragma unroll
    for (int i = 0; i < 8; i++) {
        int idx = tid + i * 128;
        CP_ASYNC16(smbase + W_SM_OFF + idx * 16, (const float4*)W + idx);
    }
    CP_COMMIT();
    CP_WAIT0();
    __syncthreads();

    // ---- epilogue: y = relu(av @ W^T + x), one row per thread ----
    {
        const int rowc = warp * 32 + lane;
        float avf[64];
        uint32_t abase = smbase + (uint32_t)(rowc * AV_STRIDE) * 4;
        #pragma unroll
        for (int i = 0; i < 32; i++) {
            uint32_t u = lds32(abase + i * 4);
            __nv_bfloat162 h = *reinterpret_cast<__nv_bfloat162*>(&u);
            float2 f = __bfloat1622float2(h);
            avf[2 * i] = f.x;
            avf[2 * i + 1] = f.y;
        }
        const int grow = blockIdx.x * 128 + rowc;
        const float4* xr4 = (const float4*)(x + base + (size_t)grow * DIM);
        float4* out4 = (float4*)(out + base + (size_t)grow * DIM);
        #pragma unroll 1
        for (int eb = 0; eb < 16; eb++) {
            float r[4];
            #pragma unroll
            for (int k = 0; k < 4; k++) {
                int e = eb * 4 + k;
                uint32_t wbase = smbase + W_SM_OFF + (uint32_t)e * 256;
                float4 acc = make_float4(0.f, 0.f, 0.f, 0.f);
                #pragma unroll
                for (int i = 0; i < 16; i++) {
                    float4 wv = lds128(wbase + i * 16);
                    acc.x = fmaf(avf[4 * i + 0], wv.x, acc.x);
                    acc.y = fmaf(avf[4 * i + 1], wv.y, acc.y);
                    acc.z = fmaf(avf[4 * i + 2], wv.z, acc.z);
                    acc.w = fmaf(avf[4 * i + 3], wv.w, acc.w);
                }
                r[k] = (acc.x + acc.y) + (acc.z + acc.w);
            }
            float4 xr = xr4[eb];
            float4 res;
            res.x = fmaxf(r[0] + xr.x, 0.0f);
            res.y = fmaxf(r[1] + xr.y, 0.0f);
            res.z = fmaxf(r[2] + xr.z, 0.0f);
            res.w = fmaxf(r[3] + xr.w, 0.0f);
            out4[eb] = res;
        }
    }
}

// ---------------------------------------------------------------------------
// Driver (graph-capturable)
// ---------------------------------------------------------------------------
extern "C" void kernel_launch(void* const* d_in, const int* in_sizes, int n_in,
                              void* d_out, int out_size) {
    const float* x      = (const float*)d_in[0];
    const float* W1     = (const float*)d_in[1];
    const float* W2     = (const float*)d_in[2];
    const float* alpha1 = (const float*)d_in[3];
    const float* alpha2 = (const float*)d_in[4];
    float* out = (float*)d_out;

    __nv_bfloat16* qk;  cudaGetSymbolAddress((void**)&qk,  g_qk);
    __nv_bfloat16* vtp; cudaGetSymbolAddress((void**)&vtp, g_vt);
    float* tmp;         cudaGetSymbolAddress((void**)&tmp, g_tmp);

    dim3 pgrid(NSEQ / 64, BH);
    dim3 agrid(NSEQ / 128, BH);

    prep_kernel<<<pgrid, 256>>>(x, qk, vtp);
    attn_mma_kernel<<<agrid, 128>>>(x, qk, vtp, W1, alpha1, tmp);
    prep_kernel<<<pgrid, 256>>>(tmp, qk, vtp);
    attn_mma_kernel<<<agrid, 128>>>(tmp, qk, vtp, W2, alpha2, out);
}